// round 11
// baseline (speedup 1.0000x reference)
#include <cuda_runtime.h>
#include <cuda_bf16.h>
#include <mma.h>
#include <cstdint>

using namespace nvcuda;

// Problem constants
static constexpr int Bb   = 4;
static constexpr int Sseq = 2048;
static constexpr int Eemb = 1024;
static constexpr int Hh   = 16;
static constexpr int Dd   = 64;
static constexpr int Mrows = Bb * Sseq;   // 8192

// Scratch (device globals: allocation-free)
__device__ float g_q[(size_t)Mrows * Eemb];
__device__ float g_k[(size_t)Mrows * Eemb];
__device__ float g_v[(size_t)Mrows * Eemb];
__device__ float g_o[(size_t)Mrows * Eemb];

// ---------------------------------------------------------------------------
// cp.async helpers
// ---------------------------------------------------------------------------
__device__ __forceinline__ void cp_async16(void* smem, const void* gmem) {
    uint32_t s = (uint32_t)__cvta_generic_to_shared(smem);
    asm volatile("cp.async.cg.shared.global [%0], [%1], 16;\n" :: "r"(s), "l"(gmem));
}
__device__ __forceinline__ void cp_commit() {
    asm volatile("cp.async.commit_group;\n");
}
template<int N> __device__ __forceinline__ void cp_wait() {
    asm volatile("cp.async.wait_group %0;\n" :: "n"(N));
}

// ---------------------------------------------------------------------------
// GEMM: C[M,N] = A[M,K] @ W[K,N] + bias[N]  (M=8192, K=N=1024), tf32 wmma
// 128x128x32 block tile, 4 warps of 64x64, 128 threads, padded smem
// (LDA=36, LDB=132), 3-stage cp.async ring (prefetch 2 tiles ahead).
// smem = 106 KB -> 2 CTAs/SM (212 KB).
// ---------------------------------------------------------------------------
static constexpr int GBM = 128, GBN = 128, GBK = 32;
static constexpr int LDA = 36;    // GBK + 4
static constexpr int LDB = 132;   // GBN + 4
static constexpr int GSTAGE = GBM * LDA + GBK * LDB;   // floats per stage
static constexpr int GEMM_SMEM_BYTES = 3 * GSTAGE * (int)sizeof(float); // 105984

__global__ __launch_bounds__(128, 2) void gemm_bias_kernel(
    const float* __restrict__ A, const float* __restrict__ W,
    const float* __restrict__ bias, float* __restrict__ C)
{
    constexpr int K = 1024, N = 1024;

    extern __shared__ float smg[];

    const int tid  = threadIdx.x;
    const int lane = tid & 31;
    const int bm   = blockIdx.y * GBM;
    const int bn   = blockIdx.x * GBN;
    const int warp = tid >> 5;         // 0..3
    const int wr   = (warp >> 1) * 64; // row offset
    const int wc   = (warp & 1) * 64;  // col offset

    auto issue_tile = [&](int kt, int buf) {
        const int k0 = kt * GBK;
        float* Ab = smg + buf * GSTAGE;
        float* Bbuf = Ab + GBM * LDA;
        #pragma unroll
        for (int t = 0; t < 8; t++) {
            int lin = tid + t * 128;
            int r = lin >> 3, c4 = lin & 7;
            cp_async16(Ab + r * LDA + c4 * 4,
                       A + (size_t)(bm + r) * K + k0 + c4 * 4);
        }
        #pragma unroll
        for (int t = 0; t < 8; t++) {
            int lin = tid + t * 128;
            int r = lin >> 5, c4 = lin & 31;
            cp_async16(Bbuf + r * LDB + c4 * 4,
                       W + (size_t)(k0 + r) * N + bn + c4 * 4);
        }
    };

    issue_tile(0, 0);
    cp_commit();
    issue_tile(1, 1);
    cp_commit();

    wmma::fragment<wmma::accumulator, 16, 16, 8, float> acc[4][4];
    #pragma unroll
    for (int i = 0; i < 4; i++)
        #pragma unroll
        for (int j = 0; j < 4; j++)
            wmma::fill_fragment(acc[i][j], 0.f);

    const int KT = K / GBK;  // 32
    int cur = 0;
    for (int kt = 0; kt < KT; kt++) {
        if (kt + 1 < KT) cp_wait<1>(); else cp_wait<0>();
        __syncthreads();   // stage cur ready; stage (cur+2)%3 free (read in kt-1)
        if (kt + 2 < KT) {
            int nb = cur + 2; if (nb >= 3) nb -= 3;
            issue_tile(kt + 2, nb);
            cp_commit();
        }

        const float* Ab = smg + cur * GSTAGE;
        const float* Bbuf = Ab + GBM * LDA;

        #pragma unroll
        for (int kk = 0; kk < GBK; kk += 8) {
            wmma::fragment<wmma::matrix_a, 16, 16, 8, wmma::precision::tf32,
                           wmma::row_major> af[4];
            #pragma unroll
            for (int i = 0; i < 4; i++) {
                wmma::load_matrix_sync(af[i], Ab + (wr + i * 16) * LDA + kk, LDA);
                #pragma unroll
                for (int t = 0; t < af[i].num_elements; t++)
                    af[i].x[t] = wmma::__float_to_tf32(af[i].x[t]);
            }
            #pragma unroll
            for (int j = 0; j < 4; j++) {
                wmma::fragment<wmma::matrix_b, 16, 16, 8, wmma::precision::tf32,
                               wmma::row_major> bf;
                wmma::load_matrix_sync(bf, Bbuf + kk * LDB + wc + j * 16, LDB);
                #pragma unroll
                for (int t = 0; t < bf.num_elements; t++)
                    bf.x[t] = wmma::__float_to_tf32(bf.x[t]);
                #pragma unroll
                for (int i = 0; i < 4; i++)
                    wmma::mma_sync(acc[i][j], af[i], bf, acc[i][j]);
            }
        }
        cur++; if (cur == 3) cur = 0;
    }

    // epilogue: add bias per element (standard m16n8 acc layout cols), store
    #pragma unroll
    for (int j = 0; j < 4; j++) {
        const int col0 = bn + wc + j * 16 + (lane & 3) * 2;
        float b0 = __ldg(bias + col0);
        float b1 = __ldg(bias + col0 + 1);
        float b8 = __ldg(bias + col0 + 8);
        float b9 = __ldg(bias + col0 + 9);
        #pragma unroll
        for (int i = 0; i < 4; i++) {
            acc[i][j].x[0] += b0; acc[i][j].x[1] += b1;
            acc[i][j].x[2] += b0; acc[i][j].x[3] += b1;
            acc[i][j].x[4] += b8; acc[i][j].x[5] += b9;
            acc[i][j].x[6] += b8; acc[i][j].x[7] += b9;
            wmma::store_matrix_sync(
                C + (size_t)(bm + wr + i * 16) * N + col0 - (lane & 3) * 2,
                acc[i][j], N, wmma::mem_row_major);
        }
    }
}

// ---------------------------------------------------------------------------
// Causal flash attention, tf32 wmma, Br=64, Bc=64, 4 warps (128 threads),
// double-buffered KV, register softmax.
// KEY CHANGE vs r10: each warp's P rows are private (it writes rows
// 16w..16w+15 of Ps and reads back exactly those rows), so the P barrier is
// only warp-scope: __syncwarp(), NOT __syncthreads(). One block barrier per
// iteration (S1, for KV buffer rotation); otherwise warps run independently,
// overlapping softmax of one warp with mma of another.
// Q converted to tf32 once at fill; P converted before store.
// 2 CTAs/SM (104 KB smem, ~224 regs).
// ---------------------------------------------------------------------------
static constexpr int LDP = 68;
static constexpr int KVTILE = 64 * LDP;        // 64x68
static constexpr int FLASH_SMEM_BYTES =
    (6 * KVTILE) * (int)sizeof(float);         // Q + 2K + 2V + P = 104448

__global__ __launch_bounds__(128, 2) void flash_kernel(
    const float* __restrict__ Q, const float* __restrict__ Kg,
    const float* __restrict__ V, float* __restrict__ O)
{
    extern __shared__ float sm[];
    float* Qs = sm;                    // 64x68 (tf32 bits)
    float* Ks = Qs + KVTILE;           // [2] 64x68
    float* Vs = Ks + 2 * KVTILE;       // [2] 64x68
    float* Ps = Vs + 2 * KVTILE;       // 64x68 (per-warp private 16-row bands)

    const int tid  = threadIdx.x;
    const int warp = tid >> 5;         // 0..3 -> rows 16w..16w+15
    const int lane = tid & 31;
    const int qt   = (Sseq / 64 - 1) - blockIdx.x;   // heavy tiles first
    const int bh   = blockIdx.y;
    const int b    = bh >> 4;
    const int h    = bh & 15;
    const float scale = 0.125f;        // 1/sqrt(64)

    const float* qb = Q + ((size_t)b * Sseq + (size_t)qt * 64) * Eemb + h * Dd;
    const float* kb = Kg + (size_t)b * Sseq * Eemb + h * Dd;
    const float* vb = V + (size_t)b * Sseq * Eemb + h * Dd;

    auto issueKV = [&](int j, int buf) {
        const float* kt = kb + (size_t)j * 64 * Eemb;
        const float* vt = vb + (size_t)j * 64 * Eemb;
        float* Kd = Ks + buf * KVTILE;
        float* Vd = Vs + buf * KVTILE;
        #pragma unroll
        for (int t = 0; t < 8; t++) {
            int lin = tid + t * 128;
            int r = lin >> 4, c4 = lin & 15;
            cp_async16(Kd + r * LDP + c4 * 4, kt + (size_t)r * Eemb + c4 * 4);
            cp_async16(Vd + r * LDP + c4 * 4, vt + (size_t)r * Eemb + c4 * 4);
        }
    };

    issueKV(0, 0);
    cp_commit();

    // Q tile (64 rows), pre-scaled AND pre-converted to tf32 (QK skips cvt)
    #pragma unroll
    for (int t = 0; t < 8; t++) {
        int lin = tid + t * 128;
        int r = lin >> 4, c4 = lin & 15;
        float4 v4 = *(const float4*)(qb + (size_t)r * Eemb + c4 * 4);
        v4.x = wmma::__float_to_tf32(v4.x * scale);
        v4.y = wmma::__float_to_tf32(v4.y * scale);
        v4.z = wmma::__float_to_tf32(v4.z * scale);
        v4.w = wmma::__float_to_tf32(v4.w * scale);
        *(float4*)(Qs + r * LDP + c4 * 4) = v4;
    }

    // register stats for this thread's two rows (lane>>2, lane>>2+8)
    float m0 = -1e30f, m1 = -1e30f, l0 = 0.f, l1 = 0.f;

    wmma::fragment<wmma::accumulator, 16, 16, 8, float> oacc[4];
    #pragma unroll
    for (int n = 0; n < 4; n++) wmma::fill_fragment(oacc[n], 0.f);

    const int warp_row0 = warp * 16;            // local row base
    const int lr0 = warp_row0 + (lane >> 2);    // this thread's local rows
    const int lr1 = lr0 + 8;
    const int nkv = qt + 1;                     // 64-key tiles

    for (int j = 0; j < nkv; j++) {
        const int cur = j & 1;

        cp_wait<0>();
        __syncthreads();  // S1: KV[cur] visible; every warp finished iter j-1
        if (j + 1 < nkv) {
            issueKV(j + 1, cur ^ 1);
            cp_commit();
        }

        const float* Kc = Ks + cur * KVTILE;
        const float* Vc = Vs + cur * KVTILE;

        // S = Q @ K^T (16x64 per warp); Q already tf32
        wmma::fragment<wmma::accumulator, 16, 16, 8, float> sacc[4];
        #pragma unroll
        for (int n = 0; n < 4; n++) wmma::fill_fragment(sacc[n], 0.f);
        #pragma unroll
        for (int kk = 0; kk < 64; kk += 8) {
            wmma::fragment<wmma::matrix_a, 16, 16, 8, wmma::precision::tf32,
                           wmma::row_major> af;
            wmma::load_matrix_sync(af, Qs + warp_row0 * LDP + kk, LDP);
            #pragma unroll
            for (int n = 0; n < 4; n++) {
                wmma::fragment<wmma::matrix_b, 16, 16, 8, wmma::precision::tf32,
                               wmma::col_major> bf;
                wmma::load_matrix_sync(bf, Kc + (n * 16) * LDP + kk, LDP);
                #pragma unroll
                for (int t = 0; t < bf.num_elements; t++)
                    bf.x[t] = wmma::__float_to_tf32(bf.x[t]);
                wmma::mma_sync(sacc[n], af, bf, sacc[n]);
            }
        }

        // causal mask (only the diagonal tile needs it)
        if (j == qt) {
            #pragma unroll
            for (int n = 0; n < 4; n++)
                #pragma unroll
                for (int t = 0; t < 8; t++) {
                    int c  = n * 16 + (lane & 3) * 2 + (t & 1) + ((t & 4) ? 8 : 0);
                    int lr = (t & 2) ? lr1 : lr0;
                    if (c > lr) sacc[n].x[t] = -1e30f;
                }
        }

        // register online softmax
        float m0n = m0, m1n = m1;
        #pragma unroll
        for (int n = 0; n < 4; n++)
            #pragma unroll
            for (int t = 0; t < 8; t++) {
                if (t & 2) m1n = fmaxf(m1n, sacc[n].x[t]);
                else       m0n = fmaxf(m0n, sacc[n].x[t]);
            }
        m0n = fmaxf(m0n, __shfl_xor_sync(0xffffffffu, m0n, 1));
        m0n = fmaxf(m0n, __shfl_xor_sync(0xffffffffu, m0n, 2));
        m1n = fmaxf(m1n, __shfl_xor_sync(0xffffffffu, m1n, 1));
        m1n = fmaxf(m1n, __shfl_xor_sync(0xffffffffu, m1n, 2));

        const float al0 = __expf(m0 - m0n);
        const float al1 = __expf(m1 - m1n);

        float s0 = 0.f, s1 = 0.f;
        #pragma unroll
        for (int n = 0; n < 4; n++)
            #pragma unroll
            for (int t = 0; t < 8; t++) {
                float p = __expf(sacc[n].x[t] - ((t & 2) ? m1n : m0n));
                sacc[n].x[t] = p;
                if (t & 2) s1 += p; else s0 += p;
            }
        s0 += __shfl_xor_sync(0xffffffffu, s0, 1);
        s0 += __shfl_xor_sync(0xffffffffu, s0, 2);
        s1 += __shfl_xor_sync(0xffffffffu, s1, 1);
        s1 += __shfl_xor_sync(0xffffffffu, s1, 2);

        m0 = m0n; m1 = m1n;
        l0 = l0 * al0 + s0;
        l1 = l1 * al1 + s1;

        // rescale O accumulators in registers
        #pragma unroll
        for (int n = 0; n < 4; n++)
            #pragma unroll
            for (int t = 0; t < 8; t++)
                oacc[n].x[t] *= (t & 2) ? al1 : al0;

        // convert P to tf32 bits, then store to this warp's PRIVATE P band
        #pragma unroll
        for (int n = 0; n < 4; n++) {
            #pragma unroll
            for (int t = 0; t < 8; t++)
                sacc[n].x[t] = wmma::__float_to_tf32(sacc[n].x[t]);
            wmma::store_matrix_sync(Ps + warp_row0 * LDP + n * 16, sacc[n],
                                    LDP, wmma::mem_row_major);
        }
        __syncwarp();  // warp-scope only: P band is private to this warp

        // O += P @ V (P already tf32)
        #pragma unroll
        for (int kk = 0; kk < 64; kk += 8) {
            wmma::fragment<wmma::matrix_a, 16, 16, 8, wmma::precision::tf32,
                           wmma::row_major> af;
            wmma::load_matrix_sync(af, Ps + warp_row0 * LDP + kk, LDP);
            #pragma unroll
            for (int n = 0; n < 4; n++) {
                wmma::fragment<wmma::matrix_b, 16, 16, 8, wmma::precision::tf32,
                               wmma::row_major> bf;
                wmma::load_matrix_sync(bf, Vc + kk * LDP + n * 16, LDP);
                #pragma unroll
                for (int t = 0; t < bf.num_elements; t++)
                    bf.x[t] = wmma::__float_to_tf32(bf.x[t]);
                wmma::mma_sync(oacc[n], af, bf, oacc[n]);
            }
        }
        // loop: next S1 orders KV rewrites after these reads
    }

    // epilogue: O /= l, store direct to gmem
    const float rl0 = 1.f / l0;
    const float rl1 = 1.f / l1;
    float* ob = O + ((size_t)b * Sseq + (size_t)qt * 64 + warp_row0) * Eemb + h * Dd;
    #pragma unroll
    for (int n = 0; n < 4; n++) {
        #pragma unroll
        for (int t = 0; t < 8; t++)
            oacc[n].x[t] *= (t & 2) ? rl1 : rl0;
        wmma::store_matrix_sync(ob + n * 16, oacc[n], Eemb, wmma::mem_row_major);
    }
}

// ---------------------------------------------------------------------------
extern "C" void kernel_launch(void* const* d_in, const int* in_sizes, int n_in,
                              void* d_out, int out_size)
{
    const float* q   = (const float*)d_in[0];
    const float* k   = (const float*)d_in[1];
    const float* v   = (const float*)d_in[2];
    const float* w_q = (const float*)d_in[3];
    const float* b_q = (const float*)d_in[4];
    const float* w_k = (const float*)d_in[5];
    const float* b_k = (const float*)d_in[6];
    const float* w_v = (const float*)d_in[7];
    const float* b_v = (const float*)d_in[8];
    const float* w_o = (const float*)d_in[9];
    const float* b_o = (const float*)d_in[10];
    float* out = (float*)d_out;

    float *gq, *gk, *gv, *go;
    cudaGetSymbolAddress((void**)&gq, g_q);
    cudaGetSymbolAddress((void**)&gk, g_k);
    cudaGetSymbolAddress((void**)&gv, g_v);
    cudaGetSymbolAddress((void**)&go, g_o);

    cudaFuncSetAttribute(gemm_bias_kernel,
                         cudaFuncAttributeMaxDynamicSharedMemorySize,
                         GEMM_SMEM_BYTES);
    cudaFuncSetAttribute(flash_kernel,
                         cudaFuncAttributeMaxDynamicSharedMemorySize,
                         FLASH_SMEM_BYTES);

    dim3 gGrid(Eemb / 128, Mrows / 128);   // (8, 64)
    gemm_bias_kernel<<<gGrid, 128, GEMM_SMEM_BYTES>>>(q, w_q, b_q, gq);
    gemm_bias_kernel<<<gGrid, 128, GEMM_SMEM_BYTES>>>(k, w_k, b_k, gk);
    gemm_bias_kernel<<<gGrid, 128, GEMM_SMEM_BYTES>>>(v, w_v, b_v, gv);

    dim3 fGrid(Sseq / 64, Bb * Hh);        // (32, 64)
    flash_kernel<<<fGrid, 128, FLASH_SMEM_BYTES>>>(gq, gk, gv, go);

    gemm_bias_kernel<<<gGrid, 128, GEMM_SMEM_BYTES>>>(go, w_o, b_o, out);
}

// round 12
// speedup vs baseline: 1.0369x; 1.0369x over previous
#include <cuda_runtime.h>
#include <cuda_bf16.h>
#include <mma.h>
#include <cstdint>

using namespace nvcuda;

// Problem constants
static constexpr int Bb   = 4;
static constexpr int Sseq = 2048;
static constexpr int Eemb = 1024;
static constexpr int Hh   = 16;
static constexpr int Dd   = 64;
static constexpr int Mrows = Bb * Sseq;   // 8192

// Scratch (device globals: allocation-free)
__device__ float g_q[(size_t)Mrows * Eemb];
__device__ float g_k[(size_t)Mrows * Eemb];
__device__ float g_v[(size_t)Mrows * Eemb];
__device__ float g_o[(size_t)Mrows * Eemb];

// ---------------------------------------------------------------------------
// cp.async helpers
// ---------------------------------------------------------------------------
__device__ __forceinline__ void cp_async16(void* smem, const void* gmem) {
    uint32_t s = (uint32_t)__cvta_generic_to_shared(smem);
    asm volatile("cp.async.cg.shared.global [%0], [%1], 16;\n" :: "r"(s), "l"(gmem));
}
__device__ __forceinline__ void cp_commit() {
    asm volatile("cp.async.commit_group;\n");
}
template<int N> __device__ __forceinline__ void cp_wait() {
    asm volatile("cp.async.wait_group %0;\n" :: "n"(N));
}

// ---------------------------------------------------------------------------
// GEMM: C[M,N] = A[M,K] @ W[K,N] + bias[N]  (M=8192, K=N=1024), tf32 wmma
// 128x128x32 block tile, 4 warps of 64x64, 128 threads, padded smem
// (LDA=36, LDB=132), 3-stage cp.async ring.
// grid.z selects one of 3 (A, W, bias, C) sets -> QKV projections fuse into
// ONE launch (1536 CTAs stream continuously instead of 3x2 quantized waves).
// ---------------------------------------------------------------------------
static constexpr int GBM = 128, GBN = 128, GBK = 32;
static constexpr int LDA = 36;    // GBK + 4
static constexpr int LDB = 132;   // GBN + 4
static constexpr int GSTAGE = GBM * LDA + GBK * LDB;   // floats per stage
static constexpr int GEMM_SMEM_BYTES = 3 * GSTAGE * (int)sizeof(float); // 105984

__global__ __launch_bounds__(128, 2) void gemm_bias_kernel(
    const float* __restrict__ A0, const float* __restrict__ A1,
    const float* __restrict__ A2,
    const float* __restrict__ W0, const float* __restrict__ W1,
    const float* __restrict__ W2,
    const float* __restrict__ bias0, const float* __restrict__ bias1,
    const float* __restrict__ bias2,
    float* __restrict__ C0, float* __restrict__ C1, float* __restrict__ C2)
{
    constexpr int K = 1024, N = 1024;

    const int z = blockIdx.z;
    const float* A    = (z == 0) ? A0 : (z == 1) ? A1 : A2;
    const float* W    = (z == 0) ? W0 : (z == 1) ? W1 : W2;
    const float* bias = (z == 0) ? bias0 : (z == 1) ? bias1 : bias2;
    float*       C    = (z == 0) ? C0 : (z == 1) ? C1 : C2;

    extern __shared__ float smg[];

    const int tid  = threadIdx.x;
    const int lane = tid & 31;
    const int bm   = blockIdx.y * GBM;
    const int bn   = blockIdx.x * GBN;
    const int warp = tid >> 5;         // 0..3
    const int wr   = (warp >> 1) * 64; // row offset
    const int wc   = (warp & 1) * 64;  // col offset

    auto issue_tile = [&](int kt, int buf) {
        const int k0 = kt * GBK;
        float* Ab = smg + buf * GSTAGE;
        float* Bbuf = Ab + GBM * LDA;
        #pragma unroll
        for (int t = 0; t < 8; t++) {
            int lin = tid + t * 128;
            int r = lin >> 3, c4 = lin & 7;
            cp_async16(Ab + r * LDA + c4 * 4,
                       A + (size_t)(bm + r) * K + k0 + c4 * 4);
        }
        #pragma unroll
        for (int t = 0; t < 8; t++) {
            int lin = tid + t * 128;
            int r = lin >> 5, c4 = lin & 31;
            cp_async16(Bbuf + r * LDB + c4 * 4,
                       W + (size_t)(k0 + r) * N + bn + c4 * 4);
        }
    };

    issue_tile(0, 0);
    cp_commit();
    issue_tile(1, 1);
    cp_commit();

    wmma::fragment<wmma::accumulator, 16, 16, 8, float> acc[4][4];
    #pragma unroll
    for (int i = 0; i < 4; i++)
        #pragma unroll
        for (int j = 0; j < 4; j++)
            wmma::fill_fragment(acc[i][j], 0.f);

    const int KT = K / GBK;  // 32
    int cur = 0;
    for (int kt = 0; kt < KT; kt++) {
        if (kt + 1 < KT) cp_wait<1>(); else cp_wait<0>();
        __syncthreads();
        if (kt + 2 < KT) {
            int nb = cur + 2; if (nb >= 3) nb -= 3;
            issue_tile(kt + 2, nb);
            cp_commit();
        }

        const float* Ab = smg + cur * GSTAGE;
        const float* Bbuf = Ab + GBM * LDA;

        #pragma unroll
        for (int kk = 0; kk < GBK; kk += 8) {
            wmma::fragment<wmma::matrix_a, 16, 16, 8, wmma::precision::tf32,
                           wmma::row_major> af[4];
            #pragma unroll
            for (int i = 0; i < 4; i++) {
                wmma::load_matrix_sync(af[i], Ab + (wr + i * 16) * LDA + kk, LDA);
                #pragma unroll
                for (int t = 0; t < af[i].num_elements; t++)
                    af[i].x[t] = wmma::__float_to_tf32(af[i].x[t]);
            }
            #pragma unroll
            for (int j = 0; j < 4; j++) {
                wmma::fragment<wmma::matrix_b, 16, 16, 8, wmma::precision::tf32,
                               wmma::row_major> bf;
                wmma::load_matrix_sync(bf, Bbuf + kk * LDB + wc + j * 16, LDB);
                #pragma unroll
                for (int t = 0; t < bf.num_elements; t++)
                    bf.x[t] = wmma::__float_to_tf32(bf.x[t]);
                #pragma unroll
                for (int i = 0; i < 4; i++)
                    wmma::mma_sync(acc[i][j], af[i], bf, acc[i][j]);
            }
        }
        cur++; if (cur == 3) cur = 0;
    }

    // epilogue: add bias per element (standard m16n8 acc layout cols), store
    #pragma unroll
    for (int j = 0; j < 4; j++) {
        const int col0 = bn + wc + j * 16 + (lane & 3) * 2;
        float b0 = __ldg(bias + col0);
        float b1 = __ldg(bias + col0 + 1);
        float b8 = __ldg(bias + col0 + 8);
        float b9 = __ldg(bias + col0 + 9);
        #pragma unroll
        for (int i = 0; i < 4; i++) {
            acc[i][j].x[0] += b0; acc[i][j].x[1] += b1;
            acc[i][j].x[2] += b0; acc[i][j].x[3] += b1;
            acc[i][j].x[4] += b8; acc[i][j].x[5] += b9;
            acc[i][j].x[6] += b8; acc[i][j].x[7] += b9;
            wmma::store_matrix_sync(
                C + (size_t)(bm + wr + i * 16) * N + col0 - (lane & 3) * 2,
                acc[i][j], N, wmma::mem_row_major);
        }
    }
}

// ---------------------------------------------------------------------------
// Causal flash attention, tf32 wmma, Br=64, Bc=64, 4 warps (128 threads).
// SOFTWARE-PIPELINED: iteration j computes QK[j], then PV[j-1], then
// softmax[j]. Softmax (exp/shfl, depends only on QK[j]) executes while
// PV[j-1]'s HMMAs drain -> critical path t_QK + max(t_sm, t_PV) instead of
// t_QK + t_sm + t_PV. Math sequence on oacc unchanged:
//   ... PV[j-1], *=alpha_j, PV[j], *=alpha_{j+1} ...
// K prefetched at S1; V prefetched at S2 (after PV's V reads); split commit
// groups with cp_wait<1> steady state. Trailing PV after the loop.
// smem = Q + 2K + 2V + P = 104 KB -> 2 CTAs/SM.
// ---------------------------------------------------------------------------
static constexpr int LDP = 68;
static constexpr int KVTILE = 64 * LDP;        // 64x68
static constexpr int FLASH_SMEM_BYTES =
    (6 * KVTILE) * (int)sizeof(float);         // 104448

__global__ __launch_bounds__(128, 2) void flash_kernel(
    const float* __restrict__ Q, const float* __restrict__ Kg,
    const float* __restrict__ V, float* __restrict__ O)
{
    extern __shared__ float sm[];
    float* Qs = sm;                    // 64x68 (tf32 bits)
    float* Ks = Qs + KVTILE;           // [2] 64x68
    float* Vs = Ks + 2 * KVTILE;       // [2] 64x68
    float* Ps = Vs + 2 * KVTILE;       // 64x68 (per-warp private 16-row bands)

    const int tid  = threadIdx.x;
    const int warp = tid >> 5;         // 0..3 -> rows 16w..16w+15
    const int lane = tid & 31;
    const int qt   = (Sseq / 64 - 1) - blockIdx.x;   // heavy tiles first
    const int bh   = blockIdx.y;
    const int b    = bh >> 4;
    const int h    = bh & 15;
    const float scale = 0.125f;        // 1/sqrt(64)

    const float* qb = Q + ((size_t)b * Sseq + (size_t)qt * 64) * Eemb + h * Dd;
    const float* kb = Kg + (size_t)b * Sseq * Eemb + h * Dd;
    const float* vb = V + (size_t)b * Sseq * Eemb + h * Dd;

    auto issueK = [&](int j, int buf) {
        const float* kt = kb + (size_t)j * 64 * Eemb;
        float* Kd = Ks + buf * KVTILE;
        #pragma unroll
        for (int t = 0; t < 8; t++) {
            int lin = tid + t * 128;
            int r = lin >> 4, c4 = lin & 15;
            cp_async16(Kd + r * LDP + c4 * 4, kt + (size_t)r * Eemb + c4 * 4);
        }
    };
    auto issueV = [&](int j, int buf) {
        const float* vt = vb + (size_t)j * 64 * Eemb;
        float* Vd = Vs + buf * KVTILE;
        #pragma unroll
        for (int t = 0; t < 8; t++) {
            int lin = tid + t * 128;
            int r = lin >> 4, c4 = lin & 15;
            cp_async16(Vd + r * LDP + c4 * 4, vt + (size_t)r * Eemb + c4 * 4);
        }
    };

    // prologue: K0, V0 as separate groups (uniform cp_wait<1> in the loop)
    issueK(0, 0); cp_commit();
    issueV(0, 0); cp_commit();

    // Q tile (64 rows), pre-scaled and pre-converted to tf32
    #pragma unroll
    for (int t = 0; t < 8; t++) {
        int lin = tid + t * 128;
        int r = lin >> 4, c4 = lin & 15;
        float4 v4 = *(const float4*)(qb + (size_t)r * Eemb + c4 * 4);
        v4.x = wmma::__float_to_tf32(v4.x * scale);
        v4.y = wmma::__float_to_tf32(v4.y * scale);
        v4.z = wmma::__float_to_tf32(v4.z * scale);
        v4.w = wmma::__float_to_tf32(v4.w * scale);
        *(float4*)(Qs + r * LDP + c4 * 4) = v4;
    }

    float m0 = -1e30f, m1 = -1e30f, l0 = 0.f, l1 = 0.f;

    wmma::fragment<wmma::accumulator, 16, 16, 8, float> oacc[4];
    #pragma unroll
    for (int n = 0; n < 4; n++) wmma::fill_fragment(oacc[n], 0.f);

    const int warp_row0 = warp * 16;
    const int lr0 = warp_row0 + (lane >> 2);
    const int lr1 = lr0 + 8;
    const int nkv = qt + 1;

    // PV for key tile jj (reads Ps band + Vs[jj&1]), accumulates into oacc
    auto do_pv = [&](int jj) {
        const float* Vc = Vs + (jj & 1) * KVTILE;
        #pragma unroll
        for (int kk = 0; kk < 64; kk += 8) {
            wmma::fragment<wmma::matrix_a, 16, 16, 8, wmma::precision::tf32,
                           wmma::row_major> af;
            wmma::load_matrix_sync(af, Ps + warp_row0 * LDP + kk, LDP);
            #pragma unroll
            for (int n = 0; n < 4; n++) {
                wmma::fragment<wmma::matrix_b, 16, 16, 8, wmma::precision::tf32,
                               wmma::row_major> bf;
                wmma::load_matrix_sync(bf, Vc + kk * LDP + n * 16, LDP);
                #pragma unroll
                for (int t = 0; t < bf.num_elements; t++)
                    bf.x[t] = wmma::__float_to_tf32(bf.x[t]);
                wmma::mma_sync(oacc[n], af, bf, oacc[n]);
            }
        }
    };

    for (int j = 0; j < nkv; j++) {
        const int cur = j & 1;

        cp_wait<1>();     // waits K[j] (and V[j-1]); leaves newest (V[j]) in flight
        __syncthreads();  // S1: K[cur] visible; K[cur^1] free (read in j-1)
        if (j + 1 < nkv) { issueK(j + 1, cur ^ 1); cp_commit(); }

        // ---- QK[j] ----
        const float* Kc = Ks + cur * KVTILE;
        wmma::fragment<wmma::accumulator, 16, 16, 8, float> sacc[4];
        #pragma unroll
        for (int n = 0; n < 4; n++) wmma::fill_fragment(sacc[n], 0.f);
        #pragma unroll
        for (int kk = 0; kk < 64; kk += 8) {
            wmma::fragment<wmma::matrix_a, 16, 16, 8, wmma::precision::tf32,
                           wmma::row_major> af;
            wmma::load_matrix_sync(af, Qs + warp_row0 * LDP + kk, LDP);
            #pragma unroll
            for (int n = 0; n < 4; n++) {
                wmma::fragment<wmma::matrix_b, 16, 16, 8, wmma::precision::tf32,
                               wmma::col_major> bf;
                wmma::load_matrix_sync(bf, Kc + (n * 16) * LDP + kk, LDP);
                #pragma unroll
                for (int t = 0; t < bf.num_elements; t++)
                    bf.x[t] = wmma::__float_to_tf32(bf.x[t]);
                wmma::mma_sync(sacc[n], af, bf, sacc[n]);
            }
        }

        // ---- PV[j-1] (independent of sacc; its HMMAs drain under softmax) ----
        if (j > 0) do_pv(j - 1);

        // ---- softmax[j] (depends on sacc only, except the oacc rescale) ----
        if (j == qt) {
            #pragma unroll
            for (int n = 0; n < 4; n++)
                #pragma unroll
                for (int t = 0; t < 8; t++) {
                    int c  = n * 16 + (lane & 3) * 2 + (t & 1) + ((t & 4) ? 8 : 0);
                    int lr = (t & 2) ? lr1 : lr0;
                    if (c > lr) sacc[n].x[t] = -1e30f;
                }
        }

        float m0n = m0, m1n = m1;
        #pragma unroll
        for (int n = 0; n < 4; n++)
            #pragma unroll
            for (int t = 0; t < 8; t++) {
                if (t & 2) m1n = fmaxf(m1n, sacc[n].x[t]);
                else       m0n = fmaxf(m0n, sacc[n].x[t]);
            }
        m0n = fmaxf(m0n, __shfl_xor_sync(0xffffffffu, m0n, 1));
        m0n = fmaxf(m0n, __shfl_xor_sync(0xffffffffu, m0n, 2));
        m1n = fmaxf(m1n, __shfl_xor_sync(0xffffffffu, m1n, 1));
        m1n = fmaxf(m1n, __shfl_xor_sync(0xffffffffu, m1n, 2));

        const float al0 = __expf(m0 - m0n);
        const float al1 = __expf(m1 - m1n);

        float s0 = 0.f, s1 = 0.f;
        #pragma unroll
        for (int n = 0; n < 4; n++)
            #pragma unroll
            for (int t = 0; t < 8; t++) {
                float p = __expf(sacc[n].x[t] - ((t & 2) ? m1n : m0n));
                sacc[n].x[t] = p;
                if (t & 2) s1 += p; else s0 += p;
            }
        s0 += __shfl_xor_sync(0xffffffffu, s0, 1);
        s0 += __shfl_xor_sync(0xffffffffu, s0, 2);
        s1 += __shfl_xor_sync(0xffffffffu, s1, 1);
        s1 += __shfl_xor_sync(0xffffffffu, s1, 2);

        m0 = m0n; m1 = m1n;
        l0 = l0 * al0 + s0;
        l1 = l1 * al1 + s1;

        // rescale O (ordered after PV[j-1] via oacc scoreboard)
        #pragma unroll
        for (int n = 0; n < 4; n++)
            #pragma unroll
            for (int t = 0; t < 8; t++)
                oacc[n].x[t] *= (t & 2) ? al1 : al0;

        // convert P to tf32, store to this warp's private band
        #pragma unroll
        for (int n = 0; n < 4; n++) {
            #pragma unroll
            for (int t = 0; t < 8; t++)
                sacc[n].x[t] = wmma::__float_to_tf32(sacc[n].x[t]);
            wmma::store_matrix_sync(Ps + warp_row0 * LDP + n * 16, sacc[n],
                                    LDP, wmma::mem_row_major);
        }

        __syncthreads();  // S2: all warps finished PV[j-1]'s V[cur^1] reads
        if (j + 1 < nkv) { issueV(j + 1, cur ^ 1); cp_commit(); }
    }

    // trailing PV for the last key tile
    cp_wait<0>();
    __syncthreads();
    do_pv(nkv - 1);

    // epilogue: O /= l, store direct to gmem
    const float rl0 = 1.f / l0;
    const float rl1 = 1.f / l1;
    float* ob = O + ((size_t)b * Sseq + (size_t)qt * 64 + warp_row0) * Eemb + h * Dd;
    #pragma unroll
    for (int n = 0; n < 4; n++) {
        #pragma unroll
        for (int t = 0; t < 8; t++)
            oacc[n].x[t] *= (t & 2) ? rl1 : rl0;
        wmma::store_matrix_sync(ob + n * 16, oacc[n], Eemb, wmma::mem_row_major);
    }
}

// ---------------------------------------------------------------------------
extern "C" void kernel_launch(void* const* d_in, const int* in_sizes, int n_in,
                              void* d_out, int out_size)
{
    const float* q   = (const float*)d_in[0];
    const float* k   = (const float*)d_in[1];
    const float* v   = (const float*)d_in[2];
    const float* w_q = (const float*)d_in[3];
    const float* b_q = (const float*)d_in[4];
    const float* w_k = (const float*)d_in[5];
    const float* b_k = (const float*)d_in[6];
    const float* w_v = (const float*)d_in[7];
    const float* b_v = (const float*)d_in[8];
    const float* w_o = (const float*)d_in[9];
    const float* b_o = (const float*)d_in[10];
    float* out = (float*)d_out;

    float *gq, *gk, *gv, *go;
    cudaGetSymbolAddress((void**)&gq, g_q);
    cudaGetSymbolAddress((void**)&gk, g_k);
    cudaGetSymbolAddress((void**)&gv, g_v);
    cudaGetSymbolAddress((void**)&go, g_o);

    cudaFuncSetAttribute(gemm_bias_kernel,
                         cudaFuncAttributeMaxDynamicSharedMemorySize,
                         GEMM_SMEM_BYTES);
    cudaFuncSetAttribute(flash_kernel,
                         cudaFuncAttributeMaxDynamicSharedMemorySize,
                         FLASH_SMEM_BYTES);

    // fused QKV projections: one launch, grid.z selects q/k/v
    dim3 gGridQKV(Eemb / 128, Mrows / 128, 3);   // (8, 64, 3)
    gemm_bias_kernel<<<gGridQKV, 128, GEMM_SMEM_BYTES>>>(
        q, k, v, w_q, w_k, w_v, b_q, b_k, b_v, gq, gk, gv);

    dim3 fGrid(Sseq / 64, Bb * Hh);              // (32, 64)
    flash_kernel<<<fGrid, 128, FLASH_SMEM_BYTES>>>(gq, gk, gv, go);

    // output projection
    dim3 gGridO(Eemb / 128, Mrows / 128, 1);
    gemm_bias_kernel<<<gGridO, 128, GEMM_SMEM_BYTES>>>(
        go, go, go, w_o, w_o, w_o, b_o, b_o, b_o, out, out, out);
}

// round 13
// speedup vs baseline: 1.1106x; 1.0711x over previous
#include <cuda_runtime.h>
#include <cuda_bf16.h>
#include <mma.h>
#include <cstdint>

using namespace nvcuda;

// Problem constants
static constexpr int Bb   = 4;
static constexpr int Sseq = 2048;
static constexpr int Eemb = 1024;
static constexpr int Hh   = 16;
static constexpr int Dd   = 64;
static constexpr int Mrows = Bb * Sseq;   // 8192
static constexpr int NBIG  = Mrows * Eemb;   // 8388608
static constexpr int NWGT  = Eemb * Eemb;    // 1048576

// Scratch (device globals: allocation-free)
__device__ float g_q[(size_t)NBIG];    // Q proj (tf32 bits)
__device__ float g_k[(size_t)NBIG];    // K proj (tf32 bits)
__device__ float g_v[(size_t)NBIG];    // V proj (tf32 bits)
__device__ float g_o[(size_t)NBIG];    // attn out (tf32 bits)
__device__ float g_cq[(size_t)NBIG];   // input q (tf32 bits)
__device__ float g_ck[(size_t)NBIG];   // input k (tf32 bits)
__device__ float g_cv[(size_t)NBIG];   // input v (tf32 bits)
__device__ float g_wq[(size_t)NWGT];   // weights (tf32 bits)
__device__ float g_wk[(size_t)NWGT];
__device__ float g_wv[(size_t)NWGT];
__device__ float g_wo[(size_t)NWGT];

// ---------------------------------------------------------------------------
// cp.async helpers
// ---------------------------------------------------------------------------
__device__ __forceinline__ void cp_async16(void* smem, const void* gmem) {
    uint32_t s = (uint32_t)__cvta_generic_to_shared(smem);
    asm volatile("cp.async.cg.shared.global [%0], [%1], 16;\n" :: "r"(s), "l"(gmem));
}
__device__ __forceinline__ void cp_commit() {
    asm volatile("cp.async.commit_group;\n");
}
template<int N> __device__ __forceinline__ void cp_wait() {
    asm volatile("cp.async.wait_group %0;\n" :: "n"(N));
}

// ---------------------------------------------------------------------------
// Elementwise fp32 -> tf32-bits converter. grid.y selects array (0..6).
// Fully HBM-bound: ~230 MB r+w ~= 60 us.
// ---------------------------------------------------------------------------
__global__ __launch_bounds__(256) void cvt_tf32_kernel(
    const float* __restrict__ s0, const float* __restrict__ s1,
    const float* __restrict__ s2, const float* __restrict__ s3,
    const float* __restrict__ s4, const float* __restrict__ s5,
    const float* __restrict__ s6,
    float* __restrict__ d0, float* __restrict__ d1, float* __restrict__ d2,
    float* __restrict__ d3, float* __restrict__ d4, float* __restrict__ d5,
    float* __restrict__ d6)
{
    const int y = blockIdx.y;
    const float* src; float* dst; int n;
    switch (y) {
        case 0: src = s0; dst = d0; n = NBIG; break;
        case 1: src = s1; dst = d1; n = NBIG; break;
        case 2: src = s2; dst = d2; n = NBIG; break;
        case 3: src = s3; dst = d3; n = NWGT; break;
        case 4: src = s4; dst = d4; n = NWGT; break;
        case 5: src = s5; dst = d5; n = NWGT; break;
        default: src = s6; dst = d6; n = NWGT; break;
    }
    const int stride = gridDim.x * blockDim.x * 4;
    for (int i = (blockIdx.x * blockDim.x + threadIdx.x) * 4; i < n; i += stride) {
        float4 v = *(const float4*)(src + i);
        v.x = wmma::__float_to_tf32(v.x);
        v.y = wmma::__float_to_tf32(v.y);
        v.z = wmma::__float_to_tf32(v.z);
        v.w = wmma::__float_to_tf32(v.w);
        *(float4*)(dst + i) = v;
    }
}

// ---------------------------------------------------------------------------
// GEMM: C[M,N] = A[M,K] @ W[K,N] + bias[N]  (M=8192, K=N=1024), tf32 wmma.
// A and W are PRE-CONVERTED tf32 bits -> ZERO cvt in the mainloop.
// cvt_out != 0: epilogue converts C to tf32 bits (for downstream mma use).
// 128x128x32 tile, 4 warps of 64x64, 128 threads, 3-stage cp.async ring,
// padded smem (LDA=36, LDB=132). grid.z selects QKV operand set.
// ---------------------------------------------------------------------------
static constexpr int GBM = 128, GBN = 128, GBK = 32;
static constexpr int LDA = 36;    // GBK + 4
static constexpr int LDB = 132;   // GBN + 4
static constexpr int GSTAGE = GBM * LDA + GBK * LDB;
static constexpr int GEMM_SMEM_BYTES = 3 * GSTAGE * (int)sizeof(float); // 105984

__global__ __launch_bounds__(128, 2) void gemm_bias_kernel(
    const float* __restrict__ A0, const float* __restrict__ A1,
    const float* __restrict__ A2,
    const float* __restrict__ W0, const float* __restrict__ W1,
    const float* __restrict__ W2,
    const float* __restrict__ bias0, const float* __restrict__ bias1,
    const float* __restrict__ bias2,
    float* __restrict__ C0, float* __restrict__ C1, float* __restrict__ C2,
    int cvt_out)
{
    constexpr int K = 1024, N = 1024;

    const int z = blockIdx.z;
    const float* A    = (z == 0) ? A0 : (z == 1) ? A1 : A2;
    const float* W    = (z == 0) ? W0 : (z == 1) ? W1 : W2;
    const float* bias = (z == 0) ? bias0 : (z == 1) ? bias1 : bias2;
    float*       C    = (z == 0) ? C0 : (z == 1) ? C1 : C2;

    extern __shared__ float smg[];

    const int tid  = threadIdx.x;
    const int lane = tid & 31;
    const int bm   = blockIdx.y * GBM;
    const int bn   = blockIdx.x * GBN;
    const int warp = tid >> 5;         // 0..3
    const int wr   = (warp >> 1) * 64;
    const int wc   = (warp & 1) * 64;

    auto issue_tile = [&](int kt, int buf) {
        const int k0 = kt * GBK;
        float* Ab = smg + buf * GSTAGE;
        float* Bbuf = Ab + GBM * LDA;
        #pragma unroll
        for (int t = 0; t < 8; t++) {
            int lin = tid + t * 128;
            int r = lin >> 3, c4 = lin & 7;
            cp_async16(Ab + r * LDA + c4 * 4,
                       A + (size_t)(bm + r) * K + k0 + c4 * 4);
        }
        #pragma unroll
        for (int t = 0; t < 8; t++) {
            int lin = tid + t * 128;
            int r = lin >> 5, c4 = lin & 31;
            cp_async16(Bbuf + r * LDB + c4 * 4,
                       W + (size_t)(k0 + r) * N + bn + c4 * 4);
        }
    };

    issue_tile(0, 0);
    cp_commit();
    issue_tile(1, 1);
    cp_commit();

    wmma::fragment<wmma::accumulator, 16, 16, 8, float> acc[4][4];
    #pragma unroll
    for (int i = 0; i < 4; i++)
        #pragma unroll
        for (int j = 0; j < 4; j++)
            wmma::fill_fragment(acc[i][j], 0.f);

    const int KT = K / GBK;  // 32
    int cur = 0;
    for (int kt = 0; kt < KT; kt++) {
        if (kt + 1 < KT) cp_wait<1>(); else cp_wait<0>();
        __syncthreads();
        if (kt + 2 < KT) {
            int nb = cur + 2; if (nb >= 3) nb -= 3;
            issue_tile(kt + 2, nb);
            cp_commit();
        }

        const float* Ab = smg + cur * GSTAGE;
        const float* Bbuf = Ab + GBM * LDA;

        #pragma unroll
        for (int kk = 0; kk < GBK; kk += 8) {
            wmma::fragment<wmma::matrix_a, 16, 16, 8, wmma::precision::tf32,
                           wmma::row_major> af[4];
            #pragma unroll
            for (int i = 0; i < 4; i++)
                wmma::load_matrix_sync(af[i], Ab + (wr + i * 16) * LDA + kk, LDA);
            #pragma unroll
            for (int j = 0; j < 4; j++) {
                wmma::fragment<wmma::matrix_b, 16, 16, 8, wmma::precision::tf32,
                               wmma::row_major> bf;
                wmma::load_matrix_sync(bf, Bbuf + kk * LDB + wc + j * 16, LDB);
                #pragma unroll
                for (int i = 0; i < 4; i++)
                    wmma::mma_sync(acc[i][j], af[i], bf, acc[i][j]);
            }
        }
        cur++; if (cur == 3) cur = 0;
    }

    // epilogue: + bias (fp32); optionally convert to tf32 bits; store
    #pragma unroll
    for (int j = 0; j < 4; j++) {
        const int col0 = bn + wc + j * 16 + (lane & 3) * 2;
        float b0 = __ldg(bias + col0);
        float b1 = __ldg(bias + col0 + 1);
        float b8 = __ldg(bias + col0 + 8);
        float b9 = __ldg(bias + col0 + 9);
        #pragma unroll
        for (int i = 0; i < 4; i++) {
            acc[i][j].x[0] += b0; acc[i][j].x[1] += b1;
            acc[i][j].x[2] += b0; acc[i][j].x[3] += b1;
            acc[i][j].x[4] += b8; acc[i][j].x[5] += b9;
            acc[i][j].x[6] += b8; acc[i][j].x[7] += b9;
            if (cvt_out) {
                #pragma unroll
                for (int t = 0; t < 8; t++)
                    acc[i][j].x[t] = wmma::__float_to_tf32(acc[i][j].x[t]);
            }
            wmma::store_matrix_sync(
                C + (size_t)(bm + wr + i * 16) * N + col0 - (lane & 3) * 2,
                acc[i][j], N, wmma::mem_row_major);
        }
    }
}

// ---------------------------------------------------------------------------
// Causal flash attention, tf32 wmma, Br=64, Bc=64, 4 warps (128 threads),
// software-pipelined (QK[j] -> PV[j-1] -> softmax[j]).
// Q/K/V arrive as PRE-CONVERTED tf32 bits -> NO cvt in the mainloop
// (Q's 0.125 scale is a power of 2: mantissa-preserving, still tf32).
// Output written as tf32 bits for the O-projection.
// smem = Q + 2K + 2V + P = 104 KB -> 2 CTAs/SM.
// ---------------------------------------------------------------------------
static constexpr int LDP = 68;
static constexpr int KVTILE = 64 * LDP;
static constexpr int FLASH_SMEM_BYTES =
    (6 * KVTILE) * (int)sizeof(float);         // 104448

__global__ __launch_bounds__(128, 2) void flash_kernel(
    const float* __restrict__ Q, const float* __restrict__ Kg,
    const float* __restrict__ V, float* __restrict__ O)
{
    extern __shared__ float sm[];
    float* Qs = sm;
    float* Ks = Qs + KVTILE;           // [2]
    float* Vs = Ks + 2 * KVTILE;       // [2]
    float* Ps = Vs + 2 * KVTILE;       // per-warp private 16-row bands

    const int tid  = threadIdx.x;
    const int warp = tid >> 5;
    const int lane = tid & 31;
    const int qt   = (Sseq / 64 - 1) - blockIdx.x;
    const int bh   = blockIdx.y;
    const int b    = bh >> 4;
    const int h    = bh & 15;
    const float scale = 0.125f;        // 1/sqrt(64), power of 2

    const float* qb = Q + ((size_t)b * Sseq + (size_t)qt * 64) * Eemb + h * Dd;
    const float* kb = Kg + (size_t)b * Sseq * Eemb + h * Dd;
    const float* vb = V + (size_t)b * Sseq * Eemb + h * Dd;

    auto issueK = [&](int j, int buf) {
        const float* kt = kb + (size_t)j * 64 * Eemb;
        float* Kd = Ks + buf * KVTILE;
        #pragma unroll
        for (int t = 0; t < 8; t++) {
            int lin = tid + t * 128;
            int r = lin >> 4, c4 = lin & 15;
            cp_async16(Kd + r * LDP + c4 * 4, kt + (size_t)r * Eemb + c4 * 4);
        }
    };
    auto issueV = [&](int j, int buf) {
        const float* vt = vb + (size_t)j * 64 * Eemb;
        float* Vd = Vs + buf * KVTILE;
        #pragma unroll
        for (int t = 0; t < 8; t++) {
            int lin = tid + t * 128;
            int r = lin >> 4, c4 = lin & 15;
            cp_async16(Vd + r * LDP + c4 * 4, vt + (size_t)r * Eemb + c4 * 4);
        }
    };

    issueK(0, 0); cp_commit();
    issueV(0, 0); cp_commit();

    // Q tile: already tf32 bits; scale by 2^-3 (exact)
    #pragma unroll
    for (int t = 0; t < 8; t++) {
        int lin = tid + t * 128;
        int r = lin >> 4, c4 = lin & 15;
        float4 v4 = *(const float4*)(qb + (size_t)r * Eemb + c4 * 4);
        v4.x *= scale; v4.y *= scale; v4.z *= scale; v4.w *= scale;
        *(float4*)(Qs + r * LDP + c4 * 4) = v4;
    }

    float m0 = -1e30f, m1 = -1e30f, l0 = 0.f, l1 = 0.f;

    wmma::fragment<wmma::accumulator, 16, 16, 8, float> oacc[4];
    #pragma unroll
    for (int n = 0; n < 4; n++) wmma::fill_fragment(oacc[n], 0.f);

    const int warp_row0 = warp * 16;
    const int lr0 = warp_row0 + (lane >> 2);
    const int lr1 = lr0 + 8;
    const int nkv = qt + 1;

    auto do_pv = [&](int jj) {
        const float* Vc = Vs + (jj & 1) * KVTILE;
        #pragma unroll
        for (int kk = 0; kk < 64; kk += 8) {
            wmma::fragment<wmma::matrix_a, 16, 16, 8, wmma::precision::tf32,
                           wmma::row_major> af;
            wmma::load_matrix_sync(af, Ps + warp_row0 * LDP + kk, LDP);
            #pragma unroll
            for (int n = 0; n < 4; n++) {
                wmma::fragment<wmma::matrix_b, 16, 16, 8, wmma::precision::tf32,
                               wmma::row_major> bf;
                wmma::load_matrix_sync(bf, Vc + kk * LDP + n * 16, LDP);
                wmma::mma_sync(oacc[n], af, bf, oacc[n]);
            }
        }
    };

    for (int j = 0; j < nkv; j++) {
        const int cur = j & 1;

        cp_wait<1>();
        __syncthreads();  // S1: K[cur] visible; K[cur^1] free
        if (j + 1 < nkv) { issueK(j + 1, cur ^ 1); cp_commit(); }

        // ---- QK[j] ----
        const float* Kc = Ks + cur * KVTILE;
        wmma::fragment<wmma::accumulator, 16, 16, 8, float> sacc[4];
        #pragma unroll
        for (int n = 0; n < 4; n++) wmma::fill_fragment(sacc[n], 0.f);
        #pragma unroll
        for (int kk = 0; kk < 64; kk += 8) {
            wmma::fragment<wmma::matrix_a, 16, 16, 8, wmma::precision::tf32,
                           wmma::row_major> af;
            wmma::load_matrix_sync(af, Qs + warp_row0 * LDP + kk, LDP);
            #pragma unroll
            for (int n = 0; n < 4; n++) {
                wmma::fragment<wmma::matrix_b, 16, 16, 8, wmma::precision::tf32,
                               wmma::col_major> bf;
                wmma::load_matrix_sync(bf, Kc + (n * 16) * LDP + kk, LDP);
                wmma::mma_sync(sacc[n], af, bf, sacc[n]);
            }
        }

        // ---- PV[j-1] (drains under softmax[j]) ----
        if (j > 0) do_pv(j - 1);

        // ---- softmax[j] ----
        if (j == qt) {
            #pragma unroll
            for (int n = 0; n < 4; n++)
                #pragma unroll
                for (int t = 0; t < 8; t++) {
                    int c  = n * 16 + (lane & 3) * 2 + (t & 1) + ((t & 4) ? 8 : 0);
                    int lr = (t & 2) ? lr1 : lr0;
                    if (c > lr) sacc[n].x[t] = -1e30f;
                }
        }

        float m0n = m0, m1n = m1;
        #pragma unroll
        for (int n = 0; n < 4; n++)
            #pragma unroll
            for (int t = 0; t < 8; t++) {
                if (t & 2) m1n = fmaxf(m1n, sacc[n].x[t]);
                else       m0n = fmaxf(m0n, sacc[n].x[t]);
            }
        m0n = fmaxf(m0n, __shfl_xor_sync(0xffffffffu, m0n, 1));
        m0n = fmaxf(m0n, __shfl_xor_sync(0xffffffffu, m0n, 2));
        m1n = fmaxf(m1n, __shfl_xor_sync(0xffffffffu, m1n, 1));
        m1n = fmaxf(m1n, __shfl_xor_sync(0xffffffffu, m1n, 2));

        const float al0 = __expf(m0 - m0n);
        const float al1 = __expf(m1 - m1n);

        float s0 = 0.f, s1 = 0.f;
        #pragma unroll
        for (int n = 0; n < 4; n++)
            #pragma unroll
            for (int t = 0; t < 8; t++) {
                float p = __expf(sacc[n].x[t] - ((t & 2) ? m1n : m0n));
                sacc[n].x[t] = p;
                if (t & 2) s1 += p; else s0 += p;
            }
        s0 += __shfl_xor_sync(0xffffffffu, s0, 1);
        s0 += __shfl_xor_sync(0xffffffffu, s0, 2);
        s1 += __shfl_xor_sync(0xffffffffu, s1, 1);
        s1 += __shfl_xor_sync(0xffffffffu, s1, 2);

        m0 = m0n; m1 = m1n;
        l0 = l0 * al0 + s0;
        l1 = l1 * al1 + s1;

        #pragma unroll
        for (int n = 0; n < 4; n++)
            #pragma unroll
            for (int t = 0; t < 8; t++)
                oacc[n].x[t] *= (t & 2) ? al1 : al0;

        // convert P to tf32, store to this warp's private band
        #pragma unroll
        for (int n = 0; n < 4; n++) {
            #pragma unroll
            for (int t = 0; t < 8; t++)
                sacc[n].x[t] = wmma::__float_to_tf32(sacc[n].x[t]);
            wmma::store_matrix_sync(Ps + warp_row0 * LDP + n * 16, sacc[n],
                                    LDP, wmma::mem_row_major);
        }

        __syncthreads();  // S2: all warps finished PV[j-1]'s V reads
        if (j + 1 < nkv) { issueV(j + 1, cur ^ 1); cp_commit(); }
    }

    cp_wait<0>();
    __syncthreads();
    do_pv(nkv - 1);

    // epilogue: O /= l, convert to tf32 bits (consumed by O-proj mma), store
    const float rl0 = 1.f / l0;
    const float rl1 = 1.f / l1;
    float* ob = O + ((size_t)b * Sseq + (size_t)qt * 64 + warp_row0) * Eemb + h * Dd;
    #pragma unroll
    for (int n = 0; n < 4; n++) {
        #pragma unroll
        for (int t = 0; t < 8; t++)
            oacc[n].x[t] = wmma::__float_to_tf32(oacc[n].x[t] * ((t & 2) ? rl1 : rl0));
        wmma::store_matrix_sync(ob + n * 16, oacc[n], Eemb, wmma::mem_row_major);
    }
}

// ---------------------------------------------------------------------------
extern "C" void kernel_launch(void* const* d_in, const int* in_sizes, int n_in,
                              void* d_out, int out_size)
{
    const float* q   = (const float*)d_in[0];
    const float* k   = (const float*)d_in[1];
    const float* v   = (const float*)d_in[2];
    const float* w_q = (const float*)d_in[3];
    const float* b_q = (const float*)d_in[4];
    const float* w_k = (const float*)d_in[5];
    const float* b_k = (const float*)d_in[6];
    const float* w_v = (const float*)d_in[7];
    const float* b_v = (const float*)d_in[8];
    const float* w_o = (const float*)d_in[9];
    const float* b_o = (const float*)d_in[10];
    float* out = (float*)d_out;

    float *gq, *gk, *gv, *go, *cq, *ck, *cv, *wq, *wk, *wv, *wo;
    cudaGetSymbolAddress((void**)&gq, g_q);
    cudaGetSymbolAddress((void**)&gk, g_k);
    cudaGetSymbolAddress((void**)&gv, g_v);
    cudaGetSymbolAddress((void**)&go, g_o);
    cudaGetSymbolAddress((void**)&cq, g_cq);
    cudaGetSymbolAddress((void**)&ck, g_ck);
    cudaGetSymbolAddress((void**)&cv, g_cv);
    cudaGetSymbolAddress((void**)&wq, g_wq);
    cudaGetSymbolAddress((void**)&wk, g_wk);
    cudaGetSymbolAddress((void**)&wv, g_wv);
    cudaGetSymbolAddress((void**)&wo, g_wo);

    cudaFuncSetAttribute(gemm_bias_kernel,
                         cudaFuncAttributeMaxDynamicSharedMemorySize,
                         GEMM_SMEM_BYTES);
    cudaFuncSetAttribute(flash_kernel,
                         cudaFuncAttributeMaxDynamicSharedMemorySize,
                         FLASH_SMEM_BYTES);

    // 0) pre-convert inputs + weights to tf32 bits
    dim3 cvtGrid(1024, 7);
    cvt_tf32_kernel<<<cvtGrid, 256>>>(q, k, v, w_q, w_k, w_v, w_o,
                                      cq, ck, cv, wq, wk, wv, wo);

    // 1) fused QKV projections (epilogue converts C to tf32 bits)
    dim3 gGridQKV(Eemb / 128, Mrows / 128, 3);
    gemm_bias_kernel<<<gGridQKV, 128, GEMM_SMEM_BYTES>>>(
        cq, ck, cv, wq, wk, wv, b_q, b_k, b_v, gq, gk, gv, 1);

    // 2) flash attention (all-tf32 operands; writes tf32 bits)
    dim3 fGrid(Sseq / 64, Bb * Hh);
    flash_kernel<<<fGrid, 128, FLASH_SMEM_BYTES>>>(gq, gk, gv, go);

    // 3) output projection (fp32 epilogue to d_out)
    dim3 gGridO(Eemb / 128, Mrows / 128, 1);
    gemm_bias_kernel<<<gGridO, 128, GEMM_SMEM_BYTES>>>(
        go, go, go, wo, wo, wo, b_o, b_o, b_o, out, out, out, 0);
}